// round 1
// baseline (speedup 1.0000x reference)
#include <cuda_runtime.h>
#include <cuda_bf16.h>
#include <cstdint>

// Problem constants
#define T_LEN   1024
#define BSZ     4
#define EMBED   1024
#define NHEADS  16
#define HDIM    64
#define NBH     (BSZ * NHEADS)      // 64
#define MROWS   (T_LEN * BSZ)       // 4096
#define SCALING 0.125f              // HDIM^-0.5

// Scratch: q/k/v in (n=B*H, t, d) layout, attn output in (t*B+b, c) layout
__device__ float g_q[NBH * T_LEN * HDIM];     // 16 MB
__device__ float g_k[NBH * T_LEN * HDIM];     // 16 MB
__device__ float g_v[NBH * T_LEN * HDIM];     // 16 MB
__device__ float g_attn[MROWS * EMBED];       // 16 MB

// ---------------------------------------------------------------------------
// Tiled fp32 GEMM:  Y[m,e] = sum_k A[m,k] * B[e,k] + bias[e]
// A: (M,K) row-major, B: (N,K) row-major (NT gemm).
// mode 0: epilogue scatters into g_q/g_k/g_v (QKV projection)
// mode 1: epilogue writes out[m*N+e] (output projection)
// ---------------------------------------------------------------------------
#define BM 64
#define BN 64
#define BK 16

__global__ __launch_bounds__(256)
void gemm_nt_kernel(const float* __restrict__ A,
                    const float* __restrict__ B,
                    const float* __restrict__ bias,
                    int M, int N, int K,
                    int mode, float* __restrict__ out)
{
    __shared__ float As[BM][BK + 1];
    __shared__ float Bs[BN][BK + 1];

    const int tid = threadIdx.x;          // 0..255
    const int ty  = tid >> 4;             // 0..15 -> row group
    const int tx  = tid & 15;             // 0..15 -> col group
    const int row0 = blockIdx.y * BM;
    const int col0 = blockIdx.x * BN;

    float acc[4][4];
#pragma unroll
    for (int i = 0; i < 4; i++)
#pragma unroll
        for (int j = 0; j < 4; j++) acc[i][j] = 0.f;

    for (int k0 = 0; k0 < K; k0 += BK) {
        // Load A tile (64x16) with float4: 256 float4s, one per thread
        {
            int r  = tid >> 2;            // 0..63
            int c4 = (tid & 3) << 2;      // 0,4,8,12
            float4 va = *reinterpret_cast<const float4*>(&A[(size_t)(row0 + r) * K + k0 + c4]);
            As[r][c4 + 0] = va.x; As[r][c4 + 1] = va.y;
            As[r][c4 + 2] = va.z; As[r][c4 + 3] = va.w;
            float4 vb = *reinterpret_cast<const float4*>(&B[(size_t)(col0 + r) * K + k0 + c4]);
            Bs[r][c4 + 0] = vb.x; Bs[r][c4 + 1] = vb.y;
            Bs[r][c4 + 2] = vb.z; Bs[r][c4 + 3] = vb.w;
        }
        __syncthreads();

#pragma unroll
        for (int kk = 0; kk < BK; kk++) {
            float a[4], b[4];
#pragma unroll
            for (int i = 0; i < 4; i++) a[i] = As[ty * 4 + i][kk];
#pragma unroll
            for (int j = 0; j < 4; j++) b[j] = Bs[tx * 4 + j][kk];
#pragma unroll
            for (int i = 0; i < 4; i++)
#pragma unroll
                for (int j = 0; j < 4; j++)
                    acc[i][j] = fmaf(a[i], b[j], acc[i][j]);
        }
        __syncthreads();
    }

    // Epilogue
#pragma unroll
    for (int i = 0; i < 4; i++) {
        int m = row0 + ty * 4 + i;
#pragma unroll
        for (int j = 0; j < 4; j++) {
            int e = col0 + tx * 4 + j;
            float v = acc[i][j] + bias[e];
            if (mode == 0) {
                // m = t*BSZ + b ; e = which*1024 + h*64 + d
                int t = m >> 2, b = m & 3;
                int which = e >> 10;
                int r = e & 1023;
                int h = r >> 6, d = r & 63;
                int n = (b << 4) + h;
                size_t off = ((size_t)n << 16) + ((size_t)t << 6) + d;  // n*65536 + t*64 + d
                if (which == 0)      g_q[off] = v * SCALING;
                else if (which == 1) g_k[off] = v;
                else                 g_v[off] = v;
            } else {
                out[(size_t)m * N + e] = v;
            }
        }
    }
}

// ---------------------------------------------------------------------------
// Fused attention: one CTA per (t, n). Scores row kept in shared memory.
// Writes attention output directly in (t*B+b, h*64+d) layout into g_attn.
// ---------------------------------------------------------------------------
__global__ __launch_bounds__(256)
void attn_kernel(const int*   __restrict__ kpm,        // (B, S)
                 const float* __restrict__ attn_mask,  // (T, S)
                 const float* __restrict__ attn_bias)  // (B*H, T, S)
{
    const int t = blockIdx.x;
    const int n = blockIdx.y;
    const int b = n >> 4;
    const int h = n & 15;
    const int tid = threadIdx.x;   // 256 threads

    __shared__ float qsh[HDIM];
    __shared__ float scores[T_LEN];
    __shared__ float red[256];
    __shared__ float pacc[4][HDIM];

    const float* qrow = g_q + ((size_t)n << 16) + ((size_t)t << 6);
    if (tid < HDIM) qsh[tid] = qrow[tid];
    __syncthreads();

    const float* Kbase  = g_k + ((size_t)n << 16);
    const float* mrow   = attn_mask + (size_t)t * T_LEN;
    const float* brow   = attn_bias + (((size_t)n * T_LEN) + t) * T_LEN;
    const int*   kpmrow = kpm + b * T_LEN;

    // --- scores ---
    for (int s = tid; s < T_LEN; s += 256) {
        const float4* kp = reinterpret_cast<const float4*>(Kbase + ((size_t)s << 6));
        float a = 0.f;
#pragma unroll
        for (int d4 = 0; d4 < 16; d4++) {
            float4 kv = kp[d4];
            a = fmaf(qsh[d4 * 4 + 0], kv.x, a);
            a = fmaf(qsh[d4 * 4 + 1], kv.y, a);
            a = fmaf(qsh[d4 * 4 + 2], kv.z, a);
            a = fmaf(qsh[d4 * 4 + 3], kv.w, a);
        }
        float sc = a + mrow[s] + brow[s];
        if (kpmrow[s]) sc = -1e30f;
        scores[s] = sc;
    }
    __syncthreads();

    // --- max reduce ---
    float m = -1e30f;
    for (int s = tid; s < T_LEN; s += 256) m = fmaxf(m, scores[s]);
    red[tid] = m;
    __syncthreads();
    for (int o = 128; o > 0; o >>= 1) {
        if (tid < o) red[tid] = fmaxf(red[tid], red[tid + o]);
        __syncthreads();
    }
    const float mx = red[0];
    __syncthreads();

    // --- exp + sum reduce ---
    float sum = 0.f;
    for (int s = tid; s < T_LEN; s += 256) {
        float e = __expf(scores[s] - mx);
        scores[s] = e;
        sum += e;
    }
    red[tid] = sum;
    __syncthreads();
    for (int o = 128; o > 0; o >>= 1) {
        if (tid < o) red[tid] += red[tid + o];
        __syncthreads();
    }
    const float inv = 1.f / red[0];

    // --- P @ V : 4 partitions over s, 64 dims over d ---
    const int d    = tid & 63;
    const int part = tid >> 6;
    const float* Vbase = g_v + ((size_t)n << 16);
    float acc = 0.f;
    const int s0 = part * 256;
#pragma unroll 4
    for (int s = s0; s < s0 + 256; s++)
        acc = fmaf(scores[s], Vbase[((size_t)s << 6) + d], acc);
    pacc[part][d] = acc;
    __syncthreads();

    if (tid < HDIM) {
        float o = (pacc[0][tid] + pacc[1][tid] + pacc[2][tid] + pacc[3][tid]) * inv;
        g_attn[(((size_t)t * BSZ) + b) * EMBED + h * HDIM + tid] = o;
    }
}

// ---------------------------------------------------------------------------
extern "C" void kernel_launch(void* const* d_in, const int* in_sizes, int n_in,
                              void* d_out, int out_size)
{
    const float* query     = (const float*)d_in[0];   // (T, B, C)
    const int*   kpm       = (const int*)  d_in[1];   // (B, S)
    const float* attn_mask = (const float*)d_in[2];   // (T, S)
    const float* attn_bias = (const float*)d_in[3];   // (B*H, T, S)
    const float* W_in      = (const float*)d_in[4];   // (3C, C)
    const float* b_in      = (const float*)d_in[5];   // (3C,)
    const float* W_out     = (const float*)d_in[6];   // (C, C)
    const float* b_out     = (const float*)d_in[7];   // (C,)
    float*       out       = (float*)d_out;           // (T, B, C)

    // 1) QKV projection + scatter to (n,t,d) scratch
    {
        dim3 grid(3 * EMBED / BN, MROWS / BM);   // (48, 64)
        gemm_nt_kernel<<<grid, 256>>>(query, W_in, b_in, MROWS, 3 * EMBED, EMBED, 0, nullptr);
    }

    // 2) Fused attention (scores + mask + bias + softmax + PV)
    {
        dim3 grid(T_LEN, NBH);                   // (1024, 64): same-n blocks adjacent -> L2 K/V reuse
        attn_kernel<<<grid, 256>>>(kpm, attn_mask, attn_bias);
    }

    // 3) Output projection (reads g_attn via device symbol)
    {
        float* attn_ptr = nullptr;
        // g_attn is referenced directly as A operand: pass device-symbol address via kernel
        // (use cudaGetSymbolAddress once per launch; it is a host-side query, capture-safe)
        cudaGetSymbolAddress((void**)&attn_ptr, g_attn);
        dim3 grid(EMBED / BN, MROWS / BM);       // (16, 64)
        gemm_nt_kernel<<<grid, 256>>>(attn_ptr, W_out, b_out, MROWS, EMBED, EMBED, 1, out);
    }
}

// round 2
// speedup vs baseline: 4.1532x; 4.1532x over previous
#include <cuda_runtime.h>
#include <cuda_bf16.h>
#include <cstdint>

// Problem constants
#define T_LEN   1024
#define BSZ     4
#define EMBED   1024
#define NHEADS  16
#define HDIM    64
#define NBH     (BSZ * NHEADS)      // 64
#define MROWS   (T_LEN * BSZ)       // 4096
#define SCALING 0.125f              // HDIM^-0.5

// Scratch: q/k/v in (n=B*H, t, d) layout, attn output in (t*B+b, c) layout
__device__ float g_q[NBH * T_LEN * HDIM];     // 16 MB
__device__ float g_k[NBH * T_LEN * HDIM];     // 16 MB
__device__ float g_v[NBH * T_LEN * HDIM];     // 16 MB
__device__ float g_attn[MROWS * EMBED];       // 16 MB

// ---------------------------------------------------------------------------
// Tiled fp32 GEMM:  Y[m,e] = sum_k A[m,k] * B[e,k] + bias[e]   (unchanged)
// ---------------------------------------------------------------------------
#define BM 64
#define BN 64
#define BK 16

__global__ __launch_bounds__(256)
void gemm_nt_kernel(const float* __restrict__ A,
                    const float* __restrict__ B,
                    const float* __restrict__ bias,
                    int M, int N, int K,
                    int mode, float* __restrict__ out)
{
    __shared__ float As[BM][BK + 1];
    __shared__ float Bs[BN][BK + 1];

    const int tid = threadIdx.x;
    const int ty  = tid >> 4;
    const int tx  = tid & 15;
    const int row0 = blockIdx.y * BM;
    const int col0 = blockIdx.x * BN;

    float acc[4][4];
#pragma unroll
    for (int i = 0; i < 4; i++)
#pragma unroll
        for (int j = 0; j < 4; j++) acc[i][j] = 0.f;

    for (int k0 = 0; k0 < K; k0 += BK) {
        {
            int r  = tid >> 2;
            int c4 = (tid & 3) << 2;
            float4 va = *reinterpret_cast<const float4*>(&A[(size_t)(row0 + r) * K + k0 + c4]);
            As[r][c4 + 0] = va.x; As[r][c4 + 1] = va.y;
            As[r][c4 + 2] = va.z; As[r][c4 + 3] = va.w;
            float4 vb = *reinterpret_cast<const float4*>(&B[(size_t)(col0 + r) * K + k0 + c4]);
            Bs[r][c4 + 0] = vb.x; Bs[r][c4 + 1] = vb.y;
            Bs[r][c4 + 2] = vb.z; Bs[r][c4 + 3] = vb.w;
        }
        __syncthreads();

#pragma unroll
        for (int kk = 0; kk < BK; kk++) {
            float a[4], b[4];
#pragma unroll
            for (int i = 0; i < 4; i++) a[i] = As[ty * 4 + i][kk];
#pragma unroll
            for (int j = 0; j < 4; j++) b[j] = Bs[tx * 4 + j][kk];
#pragma unroll
            for (int i = 0; i < 4; i++)
#pragma unroll
                for (int j = 0; j < 4; j++)
                    acc[i][j] = fmaf(a[i], b[j], acc[i][j]);
        }
        __syncthreads();
    }

#pragma unroll
    for (int i = 0; i < 4; i++) {
        int m = row0 + ty * 4 + i;
#pragma unroll
        for (int j = 0; j < 4; j++) {
            int e = col0 + tx * 4 + j;
            float v = acc[i][j] + bias[e];
            if (mode == 0) {
                int t = m >> 2, b = m & 3;
                int which = e >> 10;
                int r = e & 1023;
                int h = r >> 6, d = r & 63;
                int n = (b << 4) + h;
                size_t off = ((size_t)n << 16) + ((size_t)t << 6) + d;
                if (which == 0)      g_q[off] = v * SCALING;
                else if (which == 1) g_k[off] = v;
                else                 g_v[off] = v;
            } else {
                out[(size_t)m * N + e] = v;
            }
        }
    }
}

// ---------------------------------------------------------------------------
// Tiled flash attention: CTA = (128 query rows, head n). Online softmax.
// ---------------------------------------------------------------------------
#define BT 128
#define BS 128
#define QS_ST 66    // Qs[128][66]  (8*66 % 32 == 16 -> the two ty-groups hit different banks)
#define KT_ST 132   // Kt[64][132]  (16B aligned rows for float4 reads)
#define P_ST  130   // P [128][130] (4*130 % 32 == 8 -> PV row-group reads conflict-free)

#define SM_FLOATS (128*QS_ST + 64*KT_ST + 128*64 + 128*P_ST + 3*128 + 128)
#define SM_BYTES  (SM_FLOATS * 4)

__global__ __launch_bounds__(256, 1)
void attn_tile_kernel(const int*   __restrict__ kpm,        // (B, S)
                      const float* __restrict__ attn_mask,  // (T, S)
                      const float* __restrict__ attn_bias)  // (B*H, T, S)
{
    extern __shared__ float sm[];
    float* Qs   = sm;                       // [128][QS_ST]
    float* Kt   = Qs + 128 * QS_ST;         // [64][KT_ST] transposed
    float* Vs   = Kt + 64 * KT_ST;          // [128][64]
    float* P    = Vs + 128 * 64;            // [128][P_ST]
    float* mrow = P + 128 * P_ST;           // [128]
    float* lrow = mrow + 128;               // [128]
    float* srow = lrow + 128;               // [128]
    int*   kpms = (int*)(srow + 128);       // [128]

    const int n  = blockIdx.y;
    const int t0 = blockIdx.x * BT;
    const int b  = n >> 4, h = n & 15;
    const int tid = threadIdx.x;

    // ---- load Q tile (row-major, padded) + init softmax state ----
    {
        const float* Qg = g_q + ((size_t)n << 16) + (size_t)t0 * HDIM;
#pragma unroll
        for (int it = 0; it < 8; it++) {
            int idx = it * 256 + tid;          // 0..2047 float4s
            int row = idx >> 4;
            int c4  = idx & 15;
            float4 v = *reinterpret_cast<const float4*>(Qg + row * HDIM + c4 * 4);
            float* dst = Qs + row * QS_ST + c4 * 4;
            *reinterpret_cast<float2*>(dst)     = make_float2(v.x, v.y);
            *reinterpret_cast<float2*>(dst + 2) = make_float2(v.z, v.w);
        }
        if (tid < 128) { mrow[tid] = -1e30f; lrow[tid] = 0.f; }
    }

    // S-phase thread layout: 16x16 groups, 8x8 microtile
    const int ty = tid >> 4, tx = tid & 15;
    const int r0 = ty * 8, c0 = tx * 8;
    // PV thread layout: 32 row-groups x 8 col-groups, 4x8 microtile
    const int prg = tid >> 3, pcg = tid & 7;
    const int pr0 = prg * 4, pc0 = pcg * 8;

    float O[4][8];
#pragma unroll
    for (int i = 0; i < 4; i++)
#pragma unroll
        for (int j = 0; j < 8; j++) O[i][j] = 0.f;

    const float* Kg   = g_k + ((size_t)n << 16);
    const float* Vg   = g_v + ((size_t)n << 16);
    const int*   kpmg = kpm + b * T_LEN;

    for (int s0 = 0; s0 < T_LEN; s0 += BS) {
        __syncthreads();   // prev PV done; safe to overwrite Kt/Vs/kpms

        // kpm segment
        if (tid < 128) kpms[tid] = kpmg[s0 + tid];

        // K tile, transposed into Kt[k][s]
#pragma unroll
        for (int it = 0; it < 8; it++) {
            int idx = it * 256 + tid;          // 0..2047
            int row = idx & 127;               // s within tile (lane-consecutive)
            int c4  = idx >> 7;                // 0..15
            float4 v = *reinterpret_cast<const float4*>(Kg + (size_t)(s0 + row) * HDIM + c4 * 4);
            Kt[(c4 * 4 + 0) * KT_ST + row] = v.x;
            Kt[(c4 * 4 + 1) * KT_ST + row] = v.y;
            Kt[(c4 * 4 + 2) * KT_ST + row] = v.z;
            Kt[(c4 * 4 + 3) * KT_ST + row] = v.w;
        }
        // V tile, linear copy
        {
            const float4* Vg4 = reinterpret_cast<const float4*>(Vg + (size_t)s0 * HDIM);
            float4* Vs4 = reinterpret_cast<float4*>(Vs);
#pragma unroll
            for (int it = 0; it < 8; it++) {
                int idx = it * 256 + tid;
                Vs4[idx] = Vg4[idx];
            }
        }
        __syncthreads();

        // ---- S = Q K^T ----
        float acc[8][8];
#pragma unroll
        for (int i = 0; i < 8; i++)
#pragma unroll
            for (int j = 0; j < 8; j++) acc[i][j] = 0.f;

#pragma unroll 8
        for (int kk = 0; kk < HDIM; kk++) {
            float a[8], bb[8];
#pragma unroll
            for (int i = 0; i < 8; i++) a[i] = Qs[(r0 + i) * QS_ST + kk];
            float4 b0 = *reinterpret_cast<const float4*>(Kt + kk * KT_ST + c0);
            float4 b1 = *reinterpret_cast<const float4*>(Kt + kk * KT_ST + c0 + 4);
            bb[0] = b0.x; bb[1] = b0.y; bb[2] = b0.z; bb[3] = b0.w;
            bb[4] = b1.x; bb[5] = b1.y; bb[6] = b1.z; bb[7] = b1.w;
#pragma unroll
            for (int i = 0; i < 8; i++)
#pragma unroll
                for (int j = 0; j < 8; j++)
                    acc[i][j] = fmaf(a[i], bb[j], acc[i][j]);
        }

        // ---- mask + bias + kpm ----
        int kv[8];
#pragma unroll
        for (int j = 0; j < 8; j++) kv[j] = kpms[c0 + j];
        {
            const float* mb = attn_mask + (size_t)(t0 + r0) * T_LEN + s0 + c0;
            const float* bb2 = attn_bias + (((size_t)n * T_LEN) + (t0 + r0)) * T_LEN + s0 + c0;
#pragma unroll
            for (int i = 0; i < 8; i++) {
                float4 m0 = __ldg(reinterpret_cast<const float4*>(mb + (size_t)i * T_LEN));
                float4 m1 = __ldg(reinterpret_cast<const float4*>(mb + (size_t)i * T_LEN + 4));
                float4 q0 = __ldcs(reinterpret_cast<const float4*>(bb2 + (size_t)i * T_LEN));
                float4 q1 = __ldcs(reinterpret_cast<const float4*>(bb2 + (size_t)i * T_LEN + 4));
                float mm[8] = {m0.x+q0.x, m0.y+q0.y, m0.z+q0.z, m0.w+q0.w,
                               m1.x+q1.x, m1.y+q1.y, m1.z+q1.z, m1.w+q1.w};
#pragma unroll
                for (int j = 0; j < 8; j++)
                    acc[i][j] = kv[j] ? -1e30f : (acc[i][j] + mm[j]);
            }
        }

        // ---- online softmax (row reduce across 16 tx lanes) ----
#pragma unroll
        for (int i = 0; i < 8; i++) {
            float rm = acc[i][0];
#pragma unroll
            for (int j = 1; j < 8; j++) rm = fmaxf(rm, acc[i][j]);
#pragma unroll
            for (int off = 8; off > 0; off >>= 1)
                rm = fmaxf(rm, __shfl_xor_sync(0xffffffffu, rm, off));

            float mold = mrow[r0 + i];
            float mnew = fmaxf(mold, rm);
            float rs = 0.f;
#pragma unroll
            for (int j = 0; j < 8; j++) {
                float p = __expf(acc[i][j] - mnew);
                acc[i][j] = p;
                rs += p;
            }
#pragma unroll
            for (int off = 8; off > 0; off >>= 1)
                rs += __shfl_xor_sync(0xffffffffu, rs, off);

            if (tx == 0) {
                float sc = __expf(mold - mnew);
                srow[r0 + i] = sc;
                lrow[r0 + i] = lrow[r0 + i] * sc + rs;
                mrow[r0 + i] = mnew;
            }
            // write P row segment (float2 stores, stride P_ST)
            float* pdst = P + (r0 + i) * P_ST + c0;
#pragma unroll
            for (int u = 0; u < 4; u++)
                *reinterpret_cast<float2*>(pdst + 2 * u) = make_float2(acc[i][2*u], acc[i][2*u+1]);
        }
        __syncthreads();

        // ---- O = O*scale + P V ----
#pragma unroll
        for (int i = 0; i < 4; i++) {
            float sc = srow[pr0 + i];
#pragma unroll
            for (int j = 0; j < 8; j++) O[i][j] *= sc;
        }
#pragma unroll 4
        for (int s = 0; s < BS; s++) {
            float4 v0 = *reinterpret_cast<const float4*>(Vs + s * 64 + pc0);
            float4 v1 = *reinterpret_cast<const float4*>(Vs + s * 64 + pc0 + 4);
#pragma unroll
            for (int i = 0; i < 4; i++) {
                float p = P[(pr0 + i) * P_ST + s];
                O[i][0] = fmaf(p, v0.x, O[i][0]);
                O[i][1] = fmaf(p, v0.y, O[i][1]);
                O[i][2] = fmaf(p, v0.z, O[i][2]);
                O[i][3] = fmaf(p, v0.w, O[i][3]);
                O[i][4] = fmaf(p, v1.x, O[i][4]);
                O[i][5] = fmaf(p, v1.y, O[i][5]);
                O[i][6] = fmaf(p, v1.z, O[i][6]);
                O[i][7] = fmaf(p, v1.w, O[i][7]);
            }
        }
    }

    // ---- final normalize + write ----
#pragma unroll
    for (int i = 0; i < 4; i++) {
        float inv = 1.f / lrow[pr0 + i];
        int t = t0 + pr0 + i;
        float* dst = g_attn + ((size_t)t * BSZ + b) * EMBED + h * HDIM + pc0;
        float4 o0 = make_float4(O[i][0]*inv, O[i][1]*inv, O[i][2]*inv, O[i][3]*inv);
        float4 o1 = make_float4(O[i][4]*inv, O[i][5]*inv, O[i][6]*inv, O[i][7]*inv);
        *reinterpret_cast<float4*>(dst)     = o0;
        *reinterpret_cast<float4*>(dst + 4) = o1;
    }
}

// ---------------------------------------------------------------------------
extern "C" void kernel_launch(void* const* d_in, const int* in_sizes, int n_in,
                              void* d_out, int out_size)
{
    const float* query     = (const float*)d_in[0];
    const int*   kpm       = (const int*)  d_in[1];
    const float* attn_mask = (const float*)d_in[2];
    const float* attn_bias = (const float*)d_in[3];
    const float* W_in      = (const float*)d_in[4];
    const float* b_in      = (const float*)d_in[5];
    const float* W_out     = (const float*)d_in[6];
    const float* b_out     = (const float*)d_in[7];
    float*       out       = (float*)d_out;

    // 1) QKV projection + scatter to (n,t,d) scratch
    {
        dim3 grid(3 * EMBED / BN, MROWS / BM);
        gemm_nt_kernel<<<grid, 256>>>(query, W_in, b_in, MROWS, 3 * EMBED, EMBED, 0, nullptr);
    }

    // 2) Tiled flash attention
    {
        static bool attr_set = false;
        if (!attr_set) {
            cudaFuncSetAttribute(attn_tile_kernel,
                                 cudaFuncAttributeMaxDynamicSharedMemorySize, SM_BYTES);
            attr_set = true;
        }
        dim3 grid(T_LEN / BT, NBH);   // (8, 64)
        attn_tile_kernel<<<grid, 256, SM_BYTES>>>(kpm, attn_mask, attn_bias);
    }

    // 3) Output projection
    {
        float* attn_ptr = nullptr;
        cudaGetSymbolAddress((void**)&attn_ptr, g_attn);
        dim3 grid(EMBED / BN, MROWS / BM);
        gemm_nt_kernel<<<grid, 256>>>(attn_ptr, W_out, b_out, MROWS, EMBED, EMBED, 1, out);
    }
}

// round 4
// speedup vs baseline: 6.7317x; 1.6208x over previous
#include <cuda_runtime.h>
#include <cuda_bf16.h>
#include <cstdint>

// Problem constants
#define T_LEN   1024
#define BSZ     4
#define EMBED   1024
#define NHEADS  16
#define HDIM    64
#define NBH     (BSZ * NHEADS)      // 64
#define MROWS   (T_LEN * BSZ)       // 4096
#define SCALING 0.125f

// Scratch
__device__ float g_q[NBH * T_LEN * HDIM];
__device__ float g_k[NBH * T_LEN * HDIM];
__device__ float g_v[NBH * T_LEN * HDIM];
__device__ float g_attn[MROWS * EMBED];
// bf16 split operands
__device__ __nv_bfloat16 g_Ah[MROWS * EMBED];
__device__ __nv_bfloat16 g_Al[MROWS * EMBED];
__device__ __nv_bfloat16 g_Bh[3 * EMBED * EMBED];
__device__ __nv_bfloat16 g_Bl[3 * EMBED * EMBED];

// ---------------------------------------------------------------------------
// PTX helpers (portable: sm_80+ instructions only)
// ---------------------------------------------------------------------------
__device__ __forceinline__ uint32_t s2u(const void* p) {
    return (uint32_t)__cvta_generic_to_shared(p);
}
__device__ __forceinline__ void cp_async16(uint32_t dst, const void* src) {
    asm volatile("cp.async.cg.shared.global [%0], [%1], 16;\n" :: "r"(dst), "l"(src));
}
__device__ __forceinline__ void cp_commit() {
    asm volatile("cp.async.commit_group;\n");
}
template<int N>
__device__ __forceinline__ void cp_wait() {
    asm volatile("cp.async.wait_group %0;\n" :: "n"(N));
}
__device__ __forceinline__ void ldm_x4(uint32_t* r, uint32_t addr) {
    asm volatile("ldmatrix.sync.aligned.m8n8.x4.shared.b16 {%0,%1,%2,%3}, [%4];"
                 : "=r"(r[0]), "=r"(r[1]), "=r"(r[2]), "=r"(r[3]) : "r"(addr));
}
__device__ __forceinline__ void ldm_x2(uint32_t* r, uint32_t addr) {
    asm volatile("ldmatrix.sync.aligned.m8n8.x2.shared.b16 {%0,%1}, [%2];"
                 : "=r"(r[0]), "=r"(r[1]) : "r"(addr));
}
__device__ __forceinline__ void mma16816(float* c, const uint32_t* a, const uint32_t* b) {
    asm volatile("mma.sync.aligned.m16n8k16.row.col.f32.bf16.bf16.f32 "
                 "{%0,%1,%2,%3}, {%4,%5,%6,%7}, {%8,%9}, {%0,%1,%2,%3};"
                 : "+f"(c[0]), "+f"(c[1]), "+f"(c[2]), "+f"(c[3])
                 : "r"(a[0]), "r"(a[1]), "r"(a[2]), "r"(a[3]), "r"(b[0]), "r"(b[1]));
}

// ---------------------------------------------------------------------------
// fp32 -> (hi, lo) bf16 split
// ---------------------------------------------------------------------------
__global__ __launch_bounds__(256)
void split_kernel(const float* __restrict__ src, __nv_bfloat16* __restrict__ hi,
                  __nv_bfloat16* __restrict__ lo, int n4)
{
    int i = blockIdx.x * 256 + threadIdx.x;
    if (i >= n4) return;
    float4 v = reinterpret_cast<const float4*>(src)[i];
    __nv_bfloat16 h0 = __float2bfloat16(v.x);
    __nv_bfloat16 h1 = __float2bfloat16(v.y);
    __nv_bfloat16 h2 = __float2bfloat16(v.z);
    __nv_bfloat16 h3 = __float2bfloat16(v.w);
    __nv_bfloat16 l0 = __float2bfloat16(v.x - __bfloat162float(h0));
    __nv_bfloat16 l1 = __float2bfloat16(v.y - __bfloat162float(h1));
    __nv_bfloat16 l2 = __float2bfloat16(v.z - __bfloat162float(h2));
    __nv_bfloat16 l3 = __float2bfloat16(v.w - __bfloat162float(h3));
    __nv_bfloat162 ph0; ph0.x = h0; ph0.y = h1;
    __nv_bfloat162 ph1; ph1.x = h2; ph1.y = h3;
    __nv_bfloat162 pl0; pl0.x = l0; pl0.y = l1;
    __nv_bfloat162 pl1; pl1.x = l2; pl1.y = l3;
    reinterpret_cast<__nv_bfloat162*>(hi)[2 * i]     = ph0;
    reinterpret_cast<__nv_bfloat162*>(hi)[2 * i + 1] = ph1;
    reinterpret_cast<__nv_bfloat162*>(lo)[2 * i]     = pl0;
    reinterpret_cast<__nv_bfloat162*>(lo)[2 * i + 1] = pl1;
}

// ---------------------------------------------------------------------------
// mma.sync split-bf16 GEMM: D[m,e] = sum_k A[m,k]*B[e,k]  (fp32-accurate)
// 128x128 tile per CTA, BK=32, double-buffered cp.async, 8 warps x (64x32).
// ---------------------------------------------------------------------------
#define GK 1024
#define TM 128
#define TN 128
#define TBK 32
#define NKS (GK / TBK)          // 32
#define A_ST 40                  // bf16 stride (80 bytes, conflict-free ldmatrix)
#define TILE_B (128 * A_ST * 2)  // 10240 bytes per tile
#define STAGE_B (4 * TILE_B)     // Ah, Al, Bh, Bl
#define GEMM_SMEM (2 * STAGE_B)  // 81920

__device__ __forceinline__ void load_stage(uint32_t sbase,
    const __nv_bfloat16* __restrict__ Ah, const __nv_bfloat16* __restrict__ Al,
    const __nv_bfloat16* __restrict__ Bh, const __nv_bfloat16* __restrict__ Bl,
    int row0, int col0, int k0, int tid)
{
#pragma unroll
    for (int it = 0; it < 2; it++) {
        int idx = it * 256 + tid;          // 0..511
        int r = idx >> 2, c = idx & 3;     // row, 16B chunk
        uint32_t so = r * (A_ST * 2) + c * 16;
        size_t ga = (size_t)(row0 + r) * GK + k0 + c * 8;
        size_t gb = (size_t)(col0 + r) * GK + k0 + c * 8;
        cp_async16(sbase + 0 * TILE_B + so, Ah + ga);
        cp_async16(sbase + 1 * TILE_B + so, Al + ga);
        cp_async16(sbase + 2 * TILE_B + so, Bh + gb);
        cp_async16(sbase + 3 * TILE_B + so, Bl + gb);
    }
}

__global__ __launch_bounds__(256)
void gemm_mma(const __nv_bfloat16* __restrict__ Ah, const __nv_bfloat16* __restrict__ Al,
              const __nv_bfloat16* __restrict__ Bh, const __nv_bfloat16* __restrict__ Bl,
              const float* __restrict__ bias, int mode, float* __restrict__ out)
{
    extern __shared__ char smc[];
    const uint32_t sb = s2u(smc);
    const int tid  = threadIdx.x;
    const int lane = tid & 31;
    const int wid  = tid >> 5;
    const int wr = wid & 1;       // 2 row groups of 64
    const int wc = wid >> 1;      // 4 col groups of 32
    const int row0 = blockIdx.y * TM, col0 = blockIdx.x * TN;

    // ldmatrix lane address components
    const int a_row = lane & 15;
    const int a_k8  = (lane >> 4) * 8;
    const int b_row = lane & 7;
    const int b_k8  = ((lane >> 3) & 1) * 8;

    float acc[4][4][4];
#pragma unroll
    for (int i = 0; i < 4; i++)
#pragma unroll
        for (int j = 0; j < 4; j++)
#pragma unroll
            for (int q = 0; q < 4; q++) acc[i][j][q] = 0.f;

    load_stage(sb, Ah, Al, Bh, Bl, row0, col0, 0, tid);
    cp_commit();

    for (int ks = 0; ks < NKS; ks++) {
        const uint32_t cur = sb + (uint32_t)(ks & 1) * STAGE_B;
        if (ks + 1 < NKS) {
            load_stage(sb + (uint32_t)((ks + 1) & 1) * STAGE_B,
                       Ah, Al, Bh, Bl, row0, col0, (ks + 1) * TBK, tid);
            cp_commit();
            cp_wait<1>();
        } else {
            cp_wait<0>();
        }
        __syncthreads();

#pragma unroll
        for (int kk = 0; kk < 2; kk++) {
            const int k0 = kk * 16;
            uint32_t afh[4][4], afl[4][4];
#pragma unroll
            for (int mf = 0; mf < 4; mf++) {
                uint32_t aoff = (uint32_t)((wr * 64 + mf * 16 + a_row) * A_ST + k0 + a_k8) * 2;
                ldm_x4(afh[mf], cur + 0 * TILE_B + aoff);
                ldm_x4(afl[mf], cur + 1 * TILE_B + aoff);
            }
            uint32_t bfh[4][2], bfl[4][2];
#pragma unroll
            for (int nf = 0; nf < 4; nf++) {
                uint32_t boff = (uint32_t)((wc * 32 + nf * 8 + b_row) * A_ST + k0 + b_k8) * 2;
                ldm_x2(bfh[nf], cur + 2 * TILE_B + boff);
                ldm_x2(bfl[nf], cur + 3 * TILE_B + boff);
            }
#pragma unroll
            for (int mf = 0; mf < 4; mf++)
#pragma unroll
                for (int nf = 0; nf < 4; nf++) {
                    mma16816(acc[mf][nf], afh[mf], bfh[nf]);
                    mma16816(acc[mf][nf], afh[mf], bfl[nf]);
                    mma16816(acc[mf][nf], afl[mf], bfh[nf]);
                }
        }
        __syncthreads();
    }

    // ---- epilogue ----
    const int g = lane >> 2, tig = lane & 3;
#pragma unroll
    for (int nf = 0; nf < 4; nf++) {
        const int e = col0 + wc * 32 + nf * 8 + tig * 2;
        const float bz0 = __ldg(bias + e);
        const float bz1 = __ldg(bias + e + 1);
#pragma unroll
        for (int mf = 0; mf < 4; mf++) {
#pragma unroll
            for (int half = 0; half < 2; half++) {
                const int m = row0 + wr * 64 + mf * 16 + g + half * 8;
                float v0 = acc[mf][nf][half * 2 + 0] + bz0;
                float v1 = acc[mf][nf][half * 2 + 1] + bz1;
                if (mode == 0) {
                    const int t = m >> 2, b = m & 3;
                    const int which = e >> 10;
                    const int rem = e & 1023;
                    const int h = rem >> 6, d = rem & 63;
                    const int n = (b << 4) + h;
                    float* base = (which == 0) ? g_q : (which == 1) ? g_k : g_v;
                    if (which == 0) { v0 *= SCALING; v1 *= SCALING; }
                    *reinterpret_cast<float2*>(base + ((size_t)n << 16) + ((size_t)t << 6) + d)
                        = make_float2(v0, v1);
                } else {
                    *reinterpret_cast<float2*>(out + (size_t)m * EMBED + e)
                        = make_float2(v0, v1);
                }
            }
        }
    }
}

// ---------------------------------------------------------------------------
// Tiled flash attention (unchanged)
// ---------------------------------------------------------------------------
#define BT 128
#define BS 128
#define QS_ST 66
#define KT_ST 132
#define P_ST  130
#define SM_FLOATS (128*QS_ST + 64*KT_ST + 128*64 + 128*P_ST + 3*128 + 128)
#define SM_BYTES  (SM_FLOATS * 4)

__global__ __launch_bounds__(256, 1)
void attn_tile_kernel(const int*   __restrict__ kpm,
                      const float* __restrict__ attn_mask,
                      const float* __restrict__ attn_bias)
{
    extern __shared__ float sm[];
    float* Qs   = sm;
    float* Kt   = Qs + 128 * QS_ST;
    float* Vs   = Kt + 64 * KT_ST;
    float* P    = Vs + 128 * 64;
    float* mrow = P + 128 * P_ST;
    float* lrow = mrow + 128;
    float* srow = lrow + 128;
    int*   kpms = (int*)(srow + 128);

    const int n  = blockIdx.y;
    const int t0 = blockIdx.x * BT;
    const int b  = n >> 4, h = n & 15;
    const int tid = threadIdx.x;

    {
        const float* Qg = g_q + ((size_t)n << 16) + (size_t)t0 * HDIM;
#pragma unroll
        for (int it = 0; it < 8; it++) {
            int idx = it * 256 + tid;
            int row = idx >> 4;
            int c4  = idx & 15;
            float4 v = *reinterpret_cast<const float4*>(Qg + row * HDIM + c4 * 4);
            float* dst = Qs + row * QS_ST + c4 * 4;
            *reinterpret_cast<float2*>(dst)     = make_float2(v.x, v.y);
            *reinterpret_cast<float2*>(dst + 2) = make_float2(v.z, v.w);
        }
        if (tid < 128) { mrow[tid] = -1e30f; lrow[tid] = 0.f; }
    }

    const int ty = tid >> 4, tx = tid & 15;
    const int r0 = ty * 8, c0 = tx * 8;
    const int prg = tid >> 3, pcg = tid & 7;
    const int pr0 = prg * 4, pc0 = pcg * 8;

    float O[4][8];
#pragma unroll
    for (int i = 0; i < 4; i++)
#pragma unroll
        for (int j = 0; j < 8; j++) O[i][j] = 0.f;

    const float* Kg   = g_k + ((size_t)n << 16);
    const float* Vg   = g_v + ((size_t)n << 16);
    const int*   kpmg = kpm + b * T_LEN;

    for (int s0 = 0; s0 < T_LEN; s0 += BS) {
        __syncthreads();

        if (tid < 128) kpms[tid] = kpmg[s0 + tid];

#pragma unroll
        for (int it = 0; it < 8; it++) {
            int idx = it * 256 + tid;
            int row = idx & 127;
            int c4  = idx >> 7;
            float4 v = *reinterpret_cast<const float4*>(Kg + (size_t)(s0 + row) * HDIM + c4 * 4);
            Kt[(c4 * 4 + 0) * KT_ST + row] = v.x;
            Kt[(c4 * 4 + 1) * KT_ST + row] = v.y;
            Kt[(c4 * 4 + 2) * KT_ST + row] = v.z;
            Kt[(c4 * 4 + 3) * KT_ST + row] = v.w;
        }
        {
            const float4* Vg4 = reinterpret_cast<const float4*>(Vg + (size_t)s0 * HDIM);
            float4* Vs4 = reinterpret_cast<float4*>(Vs);
#pragma unroll
            for (int it = 0; it < 8; it++) {
                int idx = it * 256 + tid;
                Vs4[idx] = Vg4[idx];
            }
        }
        __syncthreads();

        float acc[8][8];
#pragma unroll
        for (int i = 0; i < 8; i++)
#pragma unroll
            for (int j = 0; j < 8; j++) acc[i][j] = 0.f;

#pragma unroll 8
        for (int kk = 0; kk < HDIM; kk++) {
            float a[8], bb[8];
#pragma unroll
            for (int i = 0; i < 8; i++) a[i] = Qs[(r0 + i) * QS_ST + kk];
            float4 b0 = *reinterpret_cast<const float4*>(Kt + kk * KT_ST + c0);
            float4 b1 = *reinterpret_cast<const float4*>(Kt + kk * KT_ST + c0 + 4);
            bb[0] = b0.x; bb[1] = b0.y; bb[2] = b0.z; bb[3] = b0.w;
            bb[4] = b1.x; bb[5] = b1.y; bb[6] = b1.z; bb[7] = b1.w;
#pragma unroll
            for (int i = 0; i < 8; i++)
#pragma unroll
                for (int j = 0; j < 8; j++)
                    acc[i][j] = fmaf(a[i], bb[j], acc[i][j]);
        }

        int kv[8];
#pragma unroll
        for (int j = 0; j < 8; j++) kv[j] = kpms[c0 + j];
        {
            const float* mb = attn_mask + (size_t)(t0 + r0) * T_LEN + s0 + c0;
            const float* bb2 = attn_bias + (((size_t)n * T_LEN) + (t0 + r0)) * T_LEN + s0 + c0;
#pragma unroll
            for (int i = 0; i < 8; i++) {
                float4 m0 = __ldg(reinterpret_cast<const float4*>(mb + (size_t)i * T_LEN));
                float4 m1 = __ldg(reinterpret_cast<const float4*>(mb + (size_t)i * T_LEN + 4));
                float4 q0 = __ldcs(reinterpret_cast<const float4*>(bb2 + (size_t)i * T_LEN));
                float4 q1 = __ldcs(reinterpret_cast<const float4*>(bb2 + (size_t)i * T_LEN + 4));
                float mm[8] = {m0.x+q0.x, m0.y+q0.y, m0.z+q0.z, m0.w+q0.w,
                               m1.x+q1.x, m1.y+q1.y, m1.z+q1.z, m1.w+q1.w};
#pragma unroll
                for (int j = 0; j < 8; j++)
                    acc[i][j] = kv[j] ? -1e30f : (acc[i][j] + mm[j]);
            }
        }

#pragma unroll
        for (int i = 0; i < 8; i++) {
            float rm = acc[i][0];
#pragma unroll
            for (int j = 1; j < 8; j++) rm = fmaxf(rm, acc[i][j]);
#pragma unroll
            for (int off = 8; off > 0; off >>= 1)
                rm = fmaxf(rm, __shfl_xor_sync(0xffffffffu, rm, off));

            float mold = mrow[r0 + i];
            float mnew = fmaxf(mold, rm);
            float rs = 0.f;
#pragma unroll
            for (int j = 0; j < 8; j++) {
                float p = __expf(acc[i][j] - mnew);
                acc[i][j] = p;
                rs += p;
            }
#pragma unroll
            for (int off = 8; off > 0; off >>= 1)
                rs += __shfl_xor_sync(0xffffffffu, rs, off);

            if (tx == 0) {
                float sc = __expf(mold - mnew);
                srow[r0 + i] = sc;
                lrow[r0 + i] = lrow[r0 + i] * sc + rs;
                mrow[r0 + i] = mnew;
            }
            float* pdst = P + (r0 + i) * P_ST + c0;
#pragma unroll
            for (int u = 0; u < 4; u++)
                *reinterpret_cast<float2*>(pdst + 2 * u) = make_float2(acc[i][2*u], acc[i][2*u+1]);
        }
        __syncthreads();

#pragma unroll
        for (int i = 0; i < 4; i++) {
            float sc = srow[pr0 + i];
#pragma unroll
            for (int j = 0; j < 8; j++) O[i][j] *= sc;
        }
#pragma unroll 4
        for (int s = 0; s < BS; s++) {
            float4 v0 = *reinterpret_cast<const float4*>(Vs + s * 64 + pc0);
            float4 v1 = *reinterpret_cast<const float4*>(Vs + s * 64 + pc0 + 4);
#pragma unroll
            for (int i = 0; i < 4; i++) {
                float p = P[(pr0 + i) * P_ST + s];
                O[i][0] = fmaf(p, v0.x, O[i][0]);
                O[i][1] = fmaf(p, v0.y, O[i][1]);
                O[i][2] = fmaf(p, v0.z, O[i][2]);
                O[i][3] = fmaf(p, v0.w, O[i][3]);
                O[i][4] = fmaf(p, v1.x, O[i][4]);
                O[i][5] = fmaf(p, v1.y, O[i][5]);
                O[i][6] = fmaf(p, v1.z, O[i][6]);
                O[i][7] = fmaf(p, v1.w, O[i][7]);
            }
        }
    }

#pragma unroll
    for (int i = 0; i < 4; i++) {
        float inv = 1.f / lrow[pr0 + i];
        int t = t0 + pr0 + i;
        float* dst = g_attn + ((size_t)t * BSZ + b) * EMBED + h * HDIM + pc0;
        float4 o0 = make_float4(O[i][0]*inv, O[i][1]*inv, O[i][2]*inv, O[i][3]*inv);
        float4 o1 = make_float4(O[i][4]*inv, O[i][5]*inv, O[i][6]*inv, O[i][7]*inv);
        *reinterpret_cast<float4*>(dst)     = o0;
        *reinterpret_cast<float4*>(dst + 4) = o1;
    }
}

// ---------------------------------------------------------------------------
extern "C" void kernel_launch(void* const* d_in, const int* in_sizes, int n_in,
                              void* d_out, int out_size)
{
    const float* query     = (const float*)d_in[0];
    const int*   kpm       = (const int*)  d_in[1];
    const float* attn_mask = (const float*)d_in[2];
    const float* attn_bias = (const float*)d_in[3];
    const float* W_in      = (const float*)d_in[4];
    const float* b_in      = (const float*)d_in[5];
    const float* W_out     = (const float*)d_in[6];
    const float* b_out     = (const float*)d_in[7];
    float*       out       = (float*)d_out;

    static bool attr_set = false;
    if (!attr_set) {
        cudaFuncSetAttribute(gemm_mma, cudaFuncAttributeMaxDynamicSharedMemorySize, GEMM_SMEM);
        cudaFuncSetAttribute(attn_tile_kernel, cudaFuncAttributeMaxDynamicSharedMemorySize, SM_BYTES);
        attr_set = true;
    }

    __nv_bfloat16 *Ah, *Al, *Bh, *Bl;
    float* attn_ptr;
    cudaGetSymbolAddress((void**)&Ah, g_Ah);
    cudaGetSymbolAddress((void**)&Al, g_Al);
    cudaGetSymbolAddress((void**)&Bh, g_Bh);
    cudaGetSymbolAddress((void**)&Bl, g_Bl);
    cudaGetSymbolAddress((void**)&attn_ptr, g_attn);

    // 1) split query and W_in to bf16 pairs
    split_kernel<<<MROWS * EMBED / 4 / 256, 256>>>(query, Ah, Al, MROWS * EMBED / 4);
    split_kernel<<<3 * EMBED * EMBED / 4 / 256, 256>>>(W_in, Bh, Bl, 3 * EMBED * EMBED / 4);

    // 2) QKV projection on tensor cores (+ scatter epilogue)
    {
        dim3 grid(3 * EMBED / TN, MROWS / TM);   // (24, 32)
        gemm_mma<<<grid, 256, GEMM_SMEM>>>(Ah, Al, Bh, Bl, b_in, 0, nullptr);
    }

    // 3) Flash attention
    {
        dim3 grid(T_LEN / BT, NBH);
        attn_tile_kernel<<<grid, 256, SM_BYTES>>>(kpm, attn_mask, attn_bias);
    }

    // 4) split attn output and W_out, then output projection
    split_kernel<<<MROWS * EMBED / 4 / 256, 256>>>(attn_ptr, Ah, Al, MROWS * EMBED / 4);
    split_kernel<<<EMBED * EMBED / 4 / 256, 256>>>(W_out, Bh, Bl, EMBED * EMBED / 4);
    {
        dim3 grid(EMBED / TN, MROWS / TM);       // (8, 32)
        gemm_mma<<<grid, 256, GEMM_SMEM>>>(Ah, Al, Bh, Bl, b_out, 1, out);
    }
}

// round 5
// speedup vs baseline: 11.9874x; 1.7807x over previous
#include <cuda_runtime.h>
#include <cuda_bf16.h>
#include <cstdint>

// Problem constants
#define T_LEN   1024
#define BSZ     4
#define EMBED   1024
#define NHEADS  16
#define HDIM    64
#define NBH     (BSZ * NHEADS)      // 64
#define MROWS   (T_LEN * BSZ)       // 4096
#define SCALING 0.125f

// bf16 hi/lo scratch (q scaled)
__device__ __nv_bfloat16 g_qh[NBH * T_LEN * HDIM];
__device__ __nv_bfloat16 g_ql[NBH * T_LEN * HDIM];
__device__ __nv_bfloat16 g_kh[NBH * T_LEN * HDIM];
__device__ __nv_bfloat16 g_kl[NBH * T_LEN * HDIM];
__device__ __nv_bfloat16 g_vh[NBH * T_LEN * HDIM];
__device__ __nv_bfloat16 g_vl[NBH * T_LEN * HDIM];
__device__ __nv_bfloat16 g_attnh[MROWS * EMBED];
__device__ __nv_bfloat16 g_attnl[MROWS * EMBED];
// bf16 split GEMM operands
__device__ __nv_bfloat16 g_Ah[MROWS * EMBED];
__device__ __nv_bfloat16 g_Al[MROWS * EMBED];
__device__ __nv_bfloat16 g_Bh[3 * EMBED * EMBED];
__device__ __nv_bfloat16 g_Bl[3 * EMBED * EMBED];

// ---------------------------------------------------------------------------
// PTX helpers (sm_80+ portable)
// ---------------------------------------------------------------------------
__device__ __forceinline__ uint32_t s2u(const void* p) {
    return (uint32_t)__cvta_generic_to_shared(p);
}
__device__ __forceinline__ void cp_async16(uint32_t dst, const void* src) {
    asm volatile("cp.async.cg.shared.global [%0], [%1], 16;\n" :: "r"(dst), "l"(src));
}
__device__ __forceinline__ void cp_commit() {
    asm volatile("cp.async.commit_group;\n");
}
template<int N>
__device__ __forceinline__ void cp_wait() {
    asm volatile("cp.async.wait_group %0;\n" :: "n"(N));
}
__device__ __forceinline__ void ldm_x4(uint32_t* r, uint32_t addr) {
    asm volatile("ldmatrix.sync.aligned.m8n8.x4.shared.b16 {%0,%1,%2,%3}, [%4];"
                 : "=r"(r[0]), "=r"(r[1]), "=r"(r[2]), "=r"(r[3]) : "r"(addr));
}
__device__ __forceinline__ void ldm_x2(uint32_t* r, uint32_t addr) {
    asm volatile("ldmatrix.sync.aligned.m8n8.x2.shared.b16 {%0,%1}, [%2];"
                 : "=r"(r[0]), "=r"(r[1]) : "r"(addr));
}
__device__ __forceinline__ void ldm_x2_trans(uint32_t* r, uint32_t addr) {
    asm volatile("ldmatrix.sync.aligned.m8n8.x2.trans.shared.b16 {%0,%1}, [%2];"
                 : "=r"(r[0]), "=r"(r[1]) : "r"(addr));
}
__device__ __forceinline__ void mma16816(float* c, const uint32_t* a, const uint32_t* b) {
    asm volatile("mma.sync.aligned.m16n8k16.row.col.f32.bf16.bf16.f32 "
                 "{%0,%1,%2,%3}, {%4,%5,%6,%7}, {%8,%9}, {%0,%1,%2,%3};"
                 : "+f"(c[0]), "+f"(c[1]), "+f"(c[2]), "+f"(c[3])
                 : "r"(a[0]), "r"(a[1]), "r"(a[2]), "r"(a[3]), "r"(b[0]), "r"(b[1]));
}
__device__ __host__ __forceinline__ uint32_t sw128(uint32_t off) {
    return off ^ ((off >> 3) & 0x70);
}
// pack element0=a (low half), element1=b (high half)
__device__ __forceinline__ uint32_t pack_hi2(float a, float b) {
    __nv_bfloat162 t; t.x = __float2bfloat16(a); t.y = __float2bfloat16(b);
    uint32_t r; memcpy(&r, &t, 4); return r;
}
__device__ __forceinline__ uint32_t pack_lo2(float a, float b) {
    __nv_bfloat16 ha = __float2bfloat16(a), hb = __float2bfloat16(b);
    __nv_bfloat162 t;
    t.x = __float2bfloat16(a - __bfloat162float(ha));
    t.y = __float2bfloat16(b - __bfloat162float(hb));
    uint32_t r; memcpy(&r, &t, 4); return r;
}

// ---------------------------------------------------------------------------
// fp32 -> (hi, lo) bf16 split
// ---------------------------------------------------------------------------
__global__ __launch_bounds__(256)
void split_kernel(const float* __restrict__ src, __nv_bfloat16* __restrict__ hi,
                  __nv_bfloat16* __restrict__ lo, int n4)
{
    int i = blockIdx.x * 256 + threadIdx.x;
    if (i >= n4) return;
    float4 v = reinterpret_cast<const float4*>(src)[i];
    reinterpret_cast<uint32_t*>(hi)[2 * i]     = pack_hi2(v.x, v.y);
    reinterpret_cast<uint32_t*>(hi)[2 * i + 1] = pack_hi2(v.z, v.w);
    reinterpret_cast<uint32_t*>(lo)[2 * i]     = pack_lo2(v.x, v.y);
    reinterpret_cast<uint32_t*>(lo)[2 * i + 1] = pack_lo2(v.z, v.w);
}

// ---------------------------------------------------------------------------
// mma.sync split-bf16 GEMM (proven round 4); mode 0 epilogue now writes bf16 pairs
// ---------------------------------------------------------------------------
#define GK 1024
#define TM 128
#define TN 128
#define TBK 32
#define NKS (GK / TBK)
#define A_ST 40
#define TILE_B (128 * A_ST * 2)
#define STAGE_B (4 * TILE_B)
#define GEMM_SMEM (2 * STAGE_B)

__device__ __forceinline__ void load_stage(uint32_t sbase,
    const __nv_bfloat16* __restrict__ Ah, const __nv_bfloat16* __restrict__ Al,
    const __nv_bfloat16* __restrict__ Bh, const __nv_bfloat16* __restrict__ Bl,
    int row0, int col0, int k0, int tid)
{
#pragma unroll
    for (int it = 0; it < 2; it++) {
        int idx = it * 256 + tid;
        int r = idx >> 2, c = idx & 3;
        uint32_t so = r * (A_ST * 2) + c * 16;
        size_t ga = (size_t)(row0 + r) * GK + k0 + c * 8;
        size_t gb = (size_t)(col0 + r) * GK + k0 + c * 8;
        cp_async16(sbase + 0 * TILE_B + so, Ah + ga);
        cp_async16(sbase + 1 * TILE_B + so, Al + ga);
        cp_async16(sbase + 2 * TILE_B + so, Bh + gb);
        cp_async16(sbase + 3 * TILE_B + so, Bl + gb);
    }
}

__global__ __launch_bounds__(256)
void gemm_mma(const __nv_bfloat16* __restrict__ Ah, const __nv_bfloat16* __restrict__ Al,
              const __nv_bfloat16* __restrict__ Bh, const __nv_bfloat16* __restrict__ Bl,
              const float* __restrict__ bias, int mode, float* __restrict__ out)
{
    extern __shared__ char smc[];
    const uint32_t sb = s2u(smc);
    const int tid  = threadIdx.x;
    const int lane = tid & 31;
    const int wid  = tid >> 5;
    const int wr = wid & 1;
    const int wc = wid >> 1;
    const int row0 = blockIdx.y * TM, col0 = blockIdx.x * TN;

    const int a_row = lane & 15;
    const int a_k8  = (lane >> 4) * 8;
    const int b_row = lane & 7;
    const int b_k8  = ((lane >> 3) & 1) * 8;

    float acc[4][4][4];
#pragma unroll
    for (int i = 0; i < 4; i++)
#pragma unroll
        for (int j = 0; j < 4; j++)
#pragma unroll
            for (int q = 0; q < 4; q++) acc[i][j][q] = 0.f;

    load_stage(sb, Ah, Al, Bh, Bl, row0, col0, 0, tid);
    cp_commit();

    for (int ks = 0; ks < NKS; ks++) {
        const uint32_t cur = sb + (uint32_t)(ks & 1) * STAGE_B;
        if (ks + 1 < NKS) {
            load_stage(sb + (uint32_t)((ks + 1) & 1) * STAGE_B,
                       Ah, Al, Bh, Bl, row0, col0, (ks + 1) * TBK, tid);
            cp_commit();
            cp_wait<1>();
        } else {
            cp_wait<0>();
        }
        __syncthreads();

#pragma unroll
        for (int kk = 0; kk < 2; kk++) {
            const int k0 = kk * 16;
            uint32_t afh[4][4], afl[4][4];
#pragma unroll
            for (int mf = 0; mf < 4; mf++) {
                uint32_t aoff = (uint32_t)((wr * 64 + mf * 16 + a_row) * A_ST + k0 + a_k8) * 2;
                ldm_x4(afh[mf], cur + 0 * TILE_B + aoff);
                ldm_x4(afl[mf], cur + 1 * TILE_B + aoff);
            }
            uint32_t bfh[4][2], bfl[4][2];
#pragma unroll
            for (int nf = 0; nf < 4; nf++) {
                uint32_t boff = (uint32_t)((wc * 32 + nf * 8 + b_row) * A_ST + k0 + b_k8) * 2;
                ldm_x2(bfh[nf], cur + 2 * TILE_B + boff);
                ldm_x2(bfl[nf], cur + 3 * TILE_B + boff);
            }
#pragma unroll
            for (int mf = 0; mf < 4; mf++)
#pragma unroll
                for (int nf = 0; nf < 4; nf++) {
                    mma16816(acc[mf][nf], afh[mf], bfh[nf]);
                    mma16816(acc[mf][nf], afh[mf], bfl[nf]);
                    mma16816(acc[mf][nf], afl[mf], bfh[nf]);
                }
        }
        __syncthreads();
    }

    // ---- epilogue ----
    const int g = lane >> 2, tig = lane & 3;
#pragma unroll
    for (int nf = 0; nf < 4; nf++) {
        const int e = col0 + wc * 32 + nf * 8 + tig * 2;
        const float bz0 = __ldg(bias + e);
        const float bz1 = __ldg(bias + e + 1);
#pragma unroll
        for (int mf = 0; mf < 4; mf++) {
#pragma unroll
            for (int half = 0; half < 2; half++) {
                const int m = row0 + wr * 64 + mf * 16 + g + half * 8;
                float v0 = acc[mf][nf][half * 2 + 0] + bz0;
                float v1 = acc[mf][nf][half * 2 + 1] + bz1;
                if (mode == 0) {
                    const int t = m >> 2, b = m & 3;
                    const int which = e >> 10;
                    const int rem = e & 1023;
                    const int h = rem >> 6, d = rem & 63;
                    const int n = (b << 4) + h;
                    if (which == 0) { v0 *= SCALING; v1 *= SCALING; }
                    __nv_bfloat16* dh = (which == 0) ? g_qh : (which == 1) ? g_kh : g_vh;
                    __nv_bfloat16* dl = (which == 0) ? g_ql : (which == 1) ? g_kl : g_vl;
                    size_t off = ((size_t)n << 16) + ((size_t)t << 6) + d;
                    *reinterpret_cast<uint32_t*>(dh + off) = pack_hi2(v0, v1);
                    *reinterpret_cast<uint32_t*>(dl + off) = pack_lo2(v0, v1);
                } else {
                    *reinterpret_cast<float2*>(out + (size_t)m * EMBED + e)
                        = make_float2(v0, v1);
                }
            }
        }
    }
}

// ---------------------------------------------------------------------------
// Flash attention on mma.sync (split-bf16, softmax in fragment registers)
// CTA = 128 query rows x head n; 8 warps, warp = 16 rows.
// ---------------------------------------------------------------------------
#define ABT 128
#define NBLK 8
// smem (bytes): Qh 16K | Ql 16K | 2 stages x (Kh,Kl,Vh,Vl @16K) | kpm 2x512
#define AQ_H  0
#define AQ_L  16384
#define AKV0  32768
#define AKPM  (32768 + 131072)
#define ATTN_SMEM (AKPM + 1024)

__global__ __launch_bounds__(256, 1)
void attn_mma_kernel(const int*   __restrict__ kpm,
                     const float* __restrict__ attn_mask,
                     const float* __restrict__ attn_bias)
{
    extern __shared__ char smc[];
    const uint32_t sb = s2u(smc);
    const int tid = threadIdx.x, lane = tid & 31, wid = tid >> 5;
    const int n = blockIdx.y, t0 = blockIdx.x * ABT;
    const int b = n >> 4, h = n & 15;
    const int wr0 = wid * 16;
    const int g = lane >> 2, qr = lane & 3;
    const int*   kpmg = kpm + b * T_LEN;
    const size_t nbase = (size_t)n << 16;

    // --- prologue: Q + stage 0 + kpm0 ---
    {
        const __nv_bfloat16* Qh = g_qh + nbase + (size_t)t0 * 64;
        const __nv_bfloat16* Ql = g_ql + nbase + (size_t)t0 * 64;
#pragma unroll
        for (int it = 0; it < 4; it++) {
            int idx = it * 256 + tid;           // 0..1023
            int row = idx >> 3, c = idx & 7;
            uint32_t so = sw128(row * 128 + c * 16);
            cp_async16(sb + AQ_H + so, Qh + row * 64 + c * 8);
            cp_async16(sb + AQ_L + so, Ql + row * 64 + c * 8);
        }
#pragma unroll
        for (int it = 0; it < 4; it++) {
            int idx = it * 256 + tid;
            int row = idx >> 3, c = idx & 7;
            uint32_t so = sw128(row * 128 + c * 16);
            size_t go = nbase + (size_t)row * 64 + c * 8;
            cp_async16(sb + AKV0 +     0 + so, g_kh + go);
            cp_async16(sb + AKV0 + 16384 + so, g_kl + go);
            cp_async16(sb + AKV0 + 32768 + so, g_vh + go);
            cp_async16(sb + AKV0 + 49152 + so, g_vl + go);
        }
        if (tid < 32) cp_async16(sb + AKPM + tid * 16, kpmg + tid * 4);
        cp_commit();
    }

    float m0 = -1e30f, m1 = -1e30f, l0 = 0.f, l1 = 0.f;
    float O[8][4];
#pragma unroll
    for (int i = 0; i < 8; i++)
#pragma unroll
        for (int q = 0; q < 4; q++) O[i][q] = 0.f;
    uint32_t qfh[4][4], qfl[4][4];

    for (int blk = 0; blk < NBLK; blk++) {
        // prefetch next stage
        if (blk + 1 < NBLK) {
            const int s1 = (blk + 1) * 128;
            const uint32_t nb = sb + AKV0 + (uint32_t)((blk + 1) & 1) * 65536;
#pragma unroll
            for (int it = 0; it < 4; it++) {
                int idx = it * 256 + tid;
                int row = idx >> 3, c = idx & 7;
                uint32_t so = sw128(row * 128 + c * 16);
                size_t go = nbase + (size_t)(s1 + row) * 64 + c * 8;
                cp_async16(nb +     0 + so, g_kh + go);
                cp_async16(nb + 16384 + so, g_kl + go);
                cp_async16(nb + 32768 + so, g_vh + go);
                cp_async16(nb + 49152 + so, g_vl + go);
            }
            if (tid < 32) cp_async16(sb + AKPM + ((blk + 1) & 1) * 512 + tid * 16,
                                     kpmg + s1 + tid * 4);
            cp_commit();
            cp_wait<1>();
        } else {
            cp_wait<0>();
        }
        __syncthreads();

        if (blk == 0) {
            // load Q fragments once
#pragma unroll
            for (int ks = 0; ks < 4; ks++) {
                uint32_t aoff = sw128((uint32_t)(wr0 + (lane & 15)) * 128 +
                                      (uint32_t)(ks * 16 + (lane >> 4) * 8) * 2);
                ldm_x4(qfh[ks], sb + AQ_H + aoff);
                ldm_x4(qfl[ks], sb + AQ_L + aoff);
            }
        }

        const uint32_t kbase = sb + AKV0 + (uint32_t)(blk & 1) * 65536;
        const uint32_t vbase = kbase + 32768;

        // ---- S = Q K^T (3-product split) ----
        float S[16][4];
#pragma unroll
        for (int i = 0; i < 16; i++)
#pragma unroll
            for (int q = 0; q < 4; q++) S[i][q] = 0.f;
#pragma unroll
        for (int ks = 0; ks < 4; ks++) {
#pragma unroll
            for (int nf = 0; nf < 16; nf++) {
                uint32_t boff = sw128((uint32_t)(nf * 8 + (lane & 7)) * 128 +
                                      (uint32_t)(ks * 16 + ((lane >> 3) & 1) * 8) * 2);
                uint32_t bh[2], bl[2];
                ldm_x2(bh, kbase + boff);
                ldm_x2(bl, kbase + 16384 + boff);
                mma16816(S[nf], qfh[ks], bh);
                mma16816(S[nf], qfh[ks], bl);
                mma16816(S[nf], qfl[ks], bh);
            }
        }

        // ---- mask + bias + kpm, row max ----
        const int* kpms = (const int*)(smc + AKPM + (blk & 1) * 512);
        const int s0g = blk * 128;
        const int tr0 = t0 + wr0 + g, tr1 = tr0 + 8;
        float rmax0 = -1e30f, rmax1 = -1e30f;
#pragma unroll
        for (int nf = 0; nf < 16; nf++) {
            const int sloc = nf * 8 + qr * 2;
            const int scol = s0g + sloc;
            const int k0 = kpms[sloc], k1 = kpms[sloc + 1];
            float2 ma = __ldg(reinterpret_cast<const float2*>(attn_mask + (size_t)tr0 * T_LEN + scol));
            float2 mb = __ldg(reinterpret_cast<const float2*>(attn_mask + (size_t)tr1 * T_LEN + scol));
            float2 ba = __ldcs(reinterpret_cast<const float2*>(attn_bias + ((size_t)n * T_LEN + tr0) * T_LEN + scol));
            float2 bb = __ldcs(reinterpret_cast<const float2*>(attn_bias + ((size_t)n * T_LEN + tr1) * T_LEN + scol));
            S[nf][0] = k0 ? -1e30f : S[nf][0] + ma.x + ba.x;
            S[nf][1] = k1 ? -1e30f : S[nf][1] + ma.y + ba.y;
            S[nf][2] = k0 ? -1e30f : S[nf][2] + mb.x + bb.x;
            S[nf][3] = k1 ? -1e30f : S[nf][3] + mb.y + bb.y;
            rmax0 = fmaxf(rmax0, fmaxf(S[nf][0], S[nf][1]));
            rmax1 = fmaxf(rmax1, fmaxf(S[nf][2], S[nf][3]));
        }
        rmax0 = fmaxf(rmax0, __shfl_xor_sync(0xffffffffu, rmax0, 1));
        rmax0 = fmaxf(rmax0, __shfl_xor_sync(0xffffffffu, rmax0, 2));
        rmax1 = fmaxf(rmax1, __shfl_xor_sync(0xffffffffu, rmax1, 1));
        rmax1 = fmaxf(rmax1, __shfl_xor_sync(0xffffffffu, rmax1, 2));

        const float mn0 = fmaxf(m0, rmax0), mn1 = fmaxf(m1, rmax1);
        const float es0 = __expf(m0 - mn0), es1 = __expf(m1 - mn1);
        m0 = mn0; m1 = mn1;

        float rs0 = 0.f, rs1 = 0.f;
#pragma unroll
        for (int nf = 0; nf < 16; nf++) {
            S[nf][0] = __expf(S[nf][0] - mn0);
            S[nf][1] = __expf(S[nf][1] - mn0);
            S[nf][2] = __expf(S[nf][2] - mn1);
            S[nf][3] = __expf(S[nf][3] - mn1);
            rs0 += S[nf][0] + S[nf][1];
            rs1 += S[nf][2] + S[nf][3];
        }
        rs0 += __shfl_xor_sync(0xffffffffu, rs0, 1);
        rs0 += __shfl_xor_sync(0xffffffffu, rs0, 2);
        rs1 += __shfl_xor_sync(0xffffffffu, rs1, 1);
        rs1 += __shfl_xor_sync(0xffffffffu, rs1, 2);
        l0 = l0 * es0 + rs0;
        l1 = l1 * es1 + rs1;

        // rescale O
#pragma unroll
        for (int i = 0; i < 8; i++) {
            O[i][0] *= es0; O[i][1] *= es0;
            O[i][2] *= es1; O[i][3] *= es1;
        }

        // ---- O += P V (3-product split) ----
#pragma unroll
        for (int kp = 0; kp < 8; kp++) {
            uint32_t ah[4], al[4];
            ah[0] = pack_hi2(S[2*kp][0],   S[2*kp][1]);
            ah[1] = pack_hi2(S[2*kp][2],   S[2*kp][3]);
            ah[2] = pack_hi2(S[2*kp+1][0], S[2*kp+1][1]);
            ah[3] = pack_hi2(S[2*kp+1][2], S[2*kp+1][3]);
            al[0] = pack_lo2(S[2*kp][0],   S[2*kp][1]);
            al[1] = pack_lo2(S[2*kp][2],   S[2*kp][3]);
            al[2] = pack_lo2(S[2*kp+1][0], S[2*kp+1][1]);
            al[3] = pack_lo2(S[2*kp+1][2], S[2*kp+1][3]);
#pragma unroll
            for (int nf2 = 0; nf2 < 8; nf2++) {
                uint32_t voff = sw128((uint32_t)(kp * 16 + (lane & 15)) * 128 +
                                      (uint32_t)nf2 * 16);
                uint32_t vh[2], vl[2];
                ldm_x2_trans(vh, vbase + voff);
                ldm_x2_trans(vl, vbase + 16384 + voff);
                mma16816(O[nf2], ah, vh);
                mma16816(O[nf2], ah, vl);
                mma16816(O[nf2], al, vh);
            }
        }
        __syncthreads();
    }

    // ---- normalize + write bf16 hi/lo ----
    const float inv0 = 1.f / l0, inv1 = 1.f / l1;
    const int tr0 = t0 + wr0 + g, tr1 = tr0 + 8;
    const size_t base0 = ((size_t)tr0 * BSZ + b) * EMBED + h * 64;
    const size_t base1 = ((size_t)tr1 * BSZ + b) * EMBED + h * 64;
#pragma unroll
    for (int nf2 = 0; nf2 < 8; nf2++) {
        const int d0 = nf2 * 8 + qr * 2;
        float v0 = O[nf2][0] * inv0, v1 = O[nf2][1] * inv0;
        float w0 = O[nf2][2] * inv1, w1 = O[nf2][3] * inv1;
        *reinterpret_cast<uint32_t*>(g_attnh + base0 + d0) = pack_hi2(v0, v1);
        *reinterpret_cast<uint32_t*>(g_attnl + base0 + d0) = pack_lo2(v0, v1);
        *reinterpret_cast<uint32_t*>(g_attnh + base1 + d0) = pack_hi2(w0, w1);
        *reinterpret_cast<uint32_t*>(g_attnl + base1 + d0) = pack_lo2(w0, w1);
    }
}

// ---------------------------------------------------------------------------
extern "C" void kernel_launch(void* const* d_in, const int* in_sizes, int n_in,
                              void* d_out, int out_size)
{
    const float* query     = (const float*)d_in[0];
    const int*   kpm       = (const int*)  d_in[1];
    const float* attn_mask = (const float*)d_in[2];
    const float* attn_bias = (const float*)d_in[3];
    const float* W_in      = (const float*)d_in[4];
    const float* b_in      = (const float*)d_in[5];
    const float* W_out     = (const float*)d_in[6];
    const float* b_out     = (const float*)d_in[7];
    float*       out       = (float*)d_out;

    static bool attr_set = false;
    if (!attr_set) {
        cudaFuncSetAttribute(gemm_mma, cudaFuncAttributeMaxDynamicSharedMemorySize, GEMM_SMEM);
        cudaFuncSetAttribute(attn_mma_kernel, cudaFuncAttributeMaxDynamicSharedMemorySize, ATTN_SMEM);
        attr_set = true;
    }

    __nv_bfloat16 *Ah, *Al, *Bh, *Bl, *ATh, *ATl;
    cudaGetSymbolAddress((void**)&Ah, g_Ah);
    cudaGetSymbolAddress((void**)&Al, g_Al);
    cudaGetSymbolAddress((void**)&Bh, g_Bh);
    cudaGetSymbolAddress((void**)&Bl, g_Bl);
    cudaGetSymbolAddress((void**)&ATh, g_attnh);
    cudaGetSymbolAddress((void**)&ATl, g_attnl);

    // 1) split query and W_in to bf16 pairs
    split_kernel<<<MROWS * EMBED / 4 / 256, 256>>>(query, Ah, Al, MROWS * EMBED / 4);
    split_kernel<<<3 * EMBED * EMBED / 4 / 256, 256>>>(W_in, Bh, Bl, 3 * EMBED * EMBED / 4);

    // 2) QKV projection -> bf16 hi/lo q,k,v
    {
        dim3 grid(3 * EMBED / TN, MROWS / TM);
        gemm_mma<<<grid, 256, GEMM_SMEM>>>(Ah, Al, Bh, Bl, b_in, 0, nullptr);
    }

    // 3) Flash attention on tensor cores -> bf16 hi/lo attn
    {
        dim3 grid(T_LEN / ABT, NBH);   // (8, 64)
        attn_mma_kernel<<<grid, 256, ATTN_SMEM>>>(kpm, attn_mask, attn_bias);
    }

    // 4) split W_out; output projection (A = attn bf16 pairs)
    split_kernel<<<EMBED * EMBED / 4 / 256, 256>>>(W_out, Bh, Bl, EMBED * EMBED / 4);
    {
        dim3 grid(EMBED / TN, MROWS / TM);
        gemm_mma<<<grid, 256, GEMM_SMEM>>>(ATh, ATl, Bh, Bl, b_out, 1, out);
    }
}

// round 6
// speedup vs baseline: 12.7788x; 1.0660x over previous
#include <cuda_runtime.h>
#include <cuda_bf16.h>
#include <cstdint>

// Problem constants
#define T_LEN   1024
#define BSZ     4
#define EMBED   1024
#define NHEADS  16
#define HDIM    64
#define NBH     (BSZ * NHEADS)      // 64
#define MROWS   (T_LEN * BSZ)       // 4096
#define SCALING 0.125f

// bf16 hi/lo scratch (q scaled)
__device__ __nv_bfloat16 g_qh[NBH * T_LEN * HDIM];
__device__ __nv_bfloat16 g_ql[NBH * T_LEN * HDIM];
__device__ __nv_bfloat16 g_kh[NBH * T_LEN * HDIM];
__device__ __nv_bfloat16 g_kl[NBH * T_LEN * HDIM];
__device__ __nv_bfloat16 g_vh[NBH * T_LEN * HDIM];
__device__ __nv_bfloat16 g_vl[NBH * T_LEN * HDIM];
__device__ __nv_bfloat16 g_attnh[MROWS * EMBED];
__device__ __nv_bfloat16 g_attnl[MROWS * EMBED];
// bf16 split GEMM operands
__device__ __nv_bfloat16 g_Ah[MROWS * EMBED];
__device__ __nv_bfloat16 g_Al[MROWS * EMBED];
__device__ __nv_bfloat16 g_Bh[3 * EMBED * EMBED];
__device__ __nv_bfloat16 g_Bl[3 * EMBED * EMBED];

// ---------------------------------------------------------------------------
// PTX helpers (sm_80+ portable)
// ---------------------------------------------------------------------------
__device__ __forceinline__ uint32_t s2u(const void* p) {
    return (uint32_t)__cvta_generic_to_shared(p);
}
__device__ __forceinline__ void cp_async16(uint32_t dst, const void* src) {
    asm volatile("cp.async.cg.shared.global [%0], [%1], 16;\n" :: "r"(dst), "l"(src));
}
__device__ __forceinline__ void cp_commit() {
    asm volatile("cp.async.commit_group;\n");
}
template<int N>
__device__ __forceinline__ void cp_wait() {
    asm volatile("cp.async.wait_group %0;\n" :: "n"(N));
}
__device__ __forceinline__ void ldm_x4(uint32_t* r, uint32_t addr) {
    asm volatile("ldmatrix.sync.aligned.m8n8.x4.shared.b16 {%0,%1,%2,%3}, [%4];"
                 : "=r"(r[0]), "=r"(r[1]), "=r"(r[2]), "=r"(r[3]) : "r"(addr));
}
__device__ __forceinline__ void ldm_x2(uint32_t* r, uint32_t addr) {
    asm volatile("ldmatrix.sync.aligned.m8n8.x2.shared.b16 {%0,%1}, [%2];"
                 : "=r"(r[0]), "=r"(r[1]) : "r"(addr));
}
__device__ __forceinline__ void ldm_x2_trans(uint32_t* r, uint32_t addr) {
    asm volatile("ldmatrix.sync.aligned.m8n8.x2.trans.shared.b16 {%0,%1}, [%2];"
                 : "=r"(r[0]), "=r"(r[1]) : "r"(addr));
}
__device__ __forceinline__ void mma16816(float* c, const uint32_t* a, const uint32_t* b) {
    asm volatile("mma.sync.aligned.m16n8k16.row.col.f32.bf16.bf16.f32 "
                 "{%0,%1,%2,%3}, {%4,%5,%6,%7}, {%8,%9}, {%0,%1,%2,%3};"
                 : "+f"(c[0]), "+f"(c[1]), "+f"(c[2]), "+f"(c[3])
                 : "r"(a[0]), "r"(a[1]), "r"(a[2]), "r"(a[3]), "r"(b[0]), "r"(b[1]));
}
__device__ __host__ __forceinline__ uint32_t sw128(uint32_t off) {
    return off ^ ((off >> 3) & 0x70);
}
__device__ __forceinline__ uint32_t pack_hi2(float a, float b) {
    __nv_bfloat162 t; t.x = __float2bfloat16(a); t.y = __float2bfloat16(b);
    uint32_t r; memcpy(&r, &t, 4); return r;
}
__device__ __forceinline__ uint32_t pack_lo2(float a, float b) {
    __nv_bfloat16 ha = __float2bfloat16(a), hb = __float2bfloat16(b);
    __nv_bfloat162 t;
    t.x = __float2bfloat16(a - __bfloat162float(ha));
    t.y = __float2bfloat16(b - __bfloat162float(hb));
    uint32_t r; memcpy(&r, &t, 4); return r;
}

// ---------------------------------------------------------------------------
// fp32 -> (hi, lo) bf16 split
// ---------------------------------------------------------------------------
__global__ __launch_bounds__(256)
void split_kernel(const float* __restrict__ src, __nv_bfloat16* __restrict__ hi,
                  __nv_bfloat16* __restrict__ lo, int n4)
{
    int i = blockIdx.x * 256 + threadIdx.x;
    if (i >= n4) return;
    float4 v = reinterpret_cast<const float4*>(src)[i];
    reinterpret_cast<uint32_t*>(hi)[2 * i]     = pack_hi2(v.x, v.y);
    reinterpret_cast<uint32_t*>(hi)[2 * i + 1] = pack_hi2(v.z, v.w);
    reinterpret_cast<uint32_t*>(lo)[2 * i]     = pack_lo2(v.x, v.y);
    reinterpret_cast<uint32_t*>(lo)[2 * i + 1] = pack_lo2(v.z, v.w);
}

// ---------------------------------------------------------------------------
// mma.sync split-bf16 GEMM (unchanged, proven)
// ---------------------------------------------------------------------------
#define GK 1024
#define TM 128
#define TN 128
#define TBK 32
#define NKS (GK / TBK)
#define A_ST 40
#define TILE_B (128 * A_ST * 2)
#define STAGE_B (4 * TILE_B)
#define GEMM_SMEM (2 * STAGE_B)

__device__ __forceinline__ void load_stage(uint32_t sbase,
    const __nv_bfloat16* __restrict__ Ah, const __nv_bfloat16* __restrict__ Al,
    const __nv_bfloat16* __restrict__ Bh, const __nv_bfloat16* __restrict__ Bl,
    int row0, int col0, int k0, int tid)
{
#pragma unroll
    for (int it = 0; it < 2; it++) {
        int idx = it * 256 + tid;
        int r = idx >> 2, c = idx & 3;
        uint32_t so = r * (A_ST * 2) + c * 16;
        size_t ga = (size_t)(row0 + r) * GK + k0 + c * 8;
        size_t gb = (size_t)(col0 + r) * GK + k0 + c * 8;
        cp_async16(sbase + 0 * TILE_B + so, Ah + ga);
        cp_async16(sbase + 1 * TILE_B + so, Al + ga);
        cp_async16(sbase + 2 * TILE_B + so, Bh + gb);
        cp_async16(sbase + 3 * TILE_B + so, Bl + gb);
    }
}

__global__ __launch_bounds__(256)
void gemm_mma(const __nv_bfloat16* __restrict__ Ah, const __nv_bfloat16* __restrict__ Al,
              const __nv_bfloat16* __restrict__ Bh, const __nv_bfloat16* __restrict__ Bl,
              const float* __restrict__ bias, int mode, float* __restrict__ out)
{
    extern __shared__ char smc[];
    const uint32_t sb = s2u(smc);
    const int tid  = threadIdx.x;
    const int lane = tid & 31;
    const int wid  = tid >> 5;
    const int wr = wid & 1;
    const int wc = wid >> 1;
    const int row0 = blockIdx.y * TM, col0 = blockIdx.x * TN;

    const int a_row = lane & 15;
    const int a_k8  = (lane >> 4) * 8;
    const int b_row = lane & 7;
    const int b_k8  = ((lane >> 3) & 1) * 8;

    float acc[4][4][4];
#pragma unroll
    for (int i = 0; i < 4; i++)
#pragma unroll
        for (int j = 0; j < 4; j++)
#pragma unroll
            for (int q = 0; q < 4; q++) acc[i][j][q] = 0.f;

    load_stage(sb, Ah, Al, Bh, Bl, row0, col0, 0, tid);
    cp_commit();

    for (int ks = 0; ks < NKS; ks++) {
        const uint32_t cur = sb + (uint32_t)(ks & 1) * STAGE_B;
        if (ks + 1 < NKS) {
            load_stage(sb + (uint32_t)((ks + 1) & 1) * STAGE_B,
                       Ah, Al, Bh, Bl, row0, col0, (ks + 1) * TBK, tid);
            cp_commit();
            cp_wait<1>();
        } else {
            cp_wait<0>();
        }
        __syncthreads();

#pragma unroll
        for (int kk = 0; kk < 2; kk++) {
            const int k0 = kk * 16;
            uint32_t afh[4][4], afl[4][4];
#pragma unroll
            for (int mf = 0; mf < 4; mf++) {
                uint32_t aoff = (uint32_t)((wr * 64 + mf * 16 + a_row) * A_ST + k0 + a_k8) * 2;
                ldm_x4(afh[mf], cur + 0 * TILE_B + aoff);
                ldm_x4(afl[mf], cur + 1 * TILE_B + aoff);
            }
            uint32_t bfh[4][2], bfl[4][2];
#pragma unroll
            for (int nf = 0; nf < 4; nf++) {
                uint32_t boff = (uint32_t)((wc * 32 + nf * 8 + b_row) * A_ST + k0 + b_k8) * 2;
                ldm_x2(bfh[nf], cur + 2 * TILE_B + boff);
                ldm_x2(bfl[nf], cur + 3 * TILE_B + boff);
            }
#pragma unroll
            for (int mf = 0; mf < 4; mf++)
#pragma unroll
                for (int nf = 0; nf < 4; nf++) {
                    mma16816(acc[mf][nf], afh[mf], bfh[nf]);
                    mma16816(acc[mf][nf], afh[mf], bfl[nf]);
                    mma16816(acc[mf][nf], afl[mf], bfh[nf]);
                }
        }
        __syncthreads();
    }

    const int g = lane >> 2, tig = lane & 3;
#pragma unroll
    for (int nf = 0; nf < 4; nf++) {
        const int e = col0 + wc * 32 + nf * 8 + tig * 2;
        const float bz0 = __ldg(bias + e);
        const float bz1 = __ldg(bias + e + 1);
#pragma unroll
        for (int mf = 0; mf < 4; mf++) {
#pragma unroll
            for (int half = 0; half < 2; half++) {
                const int m = row0 + wr * 64 + mf * 16 + g + half * 8;
                float v0 = acc[mf][nf][half * 2 + 0] + bz0;
                float v1 = acc[mf][nf][half * 2 + 1] + bz1;
                if (mode == 0) {
                    const int t = m >> 2, b = m & 3;
                    const int which = e >> 10;
                    const int rem = e & 1023;
                    const int h = rem >> 6, d = rem & 63;
                    const int n = (b << 4) + h;
                    if (which == 0) { v0 *= SCALING; v1 *= SCALING; }
                    __nv_bfloat16* dh = (which == 0) ? g_qh : (which == 1) ? g_kh : g_vh;
                    __nv_bfloat16* dl = (which == 0) ? g_ql : (which == 1) ? g_kl : g_vl;
                    size_t off = ((size_t)n << 16) + ((size_t)t << 6) + d;
                    *reinterpret_cast<uint32_t*>(dh + off) = pack_hi2(v0, v1);
                    *reinterpret_cast<uint32_t*>(dl + off) = pack_lo2(v0, v1);
                } else {
                    *reinterpret_cast<float2*>(out + (size_t)m * EMBED + e)
                        = make_float2(v0, v1);
                }
            }
        }
    }
}

// ---------------------------------------------------------------------------
// Flash attention on mma.sync — bias staged in smem, mask prefetched to regs.
// CTA = 128 query rows x head n; 8 warps; key blocks of 64, 16 iterations.
// ---------------------------------------------------------------------------
#define ABT 128
#define ABS 64
#define NBLK (T_LEN / ABS)   // 16
// dyn smem layout
#define AQ_H   0
#define AQ_L   16384
#define AST0   32768
// per stage: Kh 8K | Kl 8K | Vh 8K | Vl 8K | bias 128x68f (34816B) | kpm 256B
#define S_KH    0
#define S_KL    8192
#define S_VH    16384
#define S_VL    24576
#define S_BIAS  32768
#define BIAS_ST 68              // floats per bias row (272B, 16B-aligned)
#define S_KPM   (32768 + 128 * BIAS_ST * 4)   // 67584
#define AST_STRIDE (S_KPM + 256)              // 67840
#define ATTN_SMEM (AST0 + 2 * AST_STRIDE)     // 168448

__global__ __launch_bounds__(256, 1)
void attn_mma_kernel(const int*   __restrict__ kpm,
                     const float* __restrict__ attn_mask,
                     const float* __restrict__ attn_bias)
{
    extern __shared__ char smc[];
    const uint32_t sb = s2u(smc);
    const int tid = threadIdx.x, lane = tid & 31, wid = tid >> 5;
    const int n = blockIdx.y, t0 = blockIdx.x * ABT;
    const int b = n >> 4, h = n & 15;
    const int wr0 = wid * 16;
    const int g = lane >> 2, qr = lane & 3;
    const int*   kpmg = kpm + b * T_LEN;
    const size_t nbase = (size_t)n << 16;
    const float* biasg = attn_bias + (size_t)n * T_LEN * T_LEN;

    // stage loader (KV + bias + kpm for key block s0 = stg_idx*64)
    auto load_kv_stage = [&](int blk) {
        const int s0 = blk * ABS;
        const uint32_t B = sb + AST0 + (uint32_t)(blk & 1) * AST_STRIDE;
        // KV: 4 arrays x 64 rows x 8 chunks = 2048 chunks -> 8/thread
#pragma unroll
        for (int it = 0; it < 2; it++) {
            int idx = it * 256 + tid;           // 0..511
            int row = idx >> 3, c = idx & 7;
            uint32_t so = sw128(row * 128 + c * 16);
            size_t go = nbase + (size_t)(s0 + row) * 64 + c * 8;
            cp_async16(B + S_KH + so, g_kh + go);
            cp_async16(B + S_KL + so, g_kl + go);
            cp_async16(B + S_VH + so, g_vh + go);
            cp_async16(B + S_VL + so, g_vl + go);
        }
        // bias: 128 rows x 16 chunks = 2048 -> 8/thread
#pragma unroll
        for (int it = 0; it < 8; it++) {
            int idx = it * 256 + tid;
            int row = idx >> 4, c = idx & 15;
            cp_async16(B + S_BIAS + row * (BIAS_ST * 4) + c * 16,
                       biasg + (size_t)(t0 + row) * T_LEN + s0 + c * 4);
        }
        if (tid < 16) cp_async16(B + S_KPM + tid * 16, kpmg + s0 + tid * 4);
    };

    // --- prologue: Q + stage 0 ---
    {
        const __nv_bfloat16* Qh = g_qh + nbase + (size_t)t0 * 64;
        const __nv_bfloat16* Ql = g_ql + nbase + (size_t)t0 * 64;
#pragma unroll
        for (int it = 0; it < 4; it++) {
            int idx = it * 256 + tid;
            int row = idx >> 3, c = idx & 7;
            uint32_t so = sw128(row * 128 + c * 16);
            cp_async16(sb + AQ_H + so, Qh + row * 64 + c * 8);
            cp_async16(sb + AQ_L + so, Ql + row * 64 + c * 8);
        }
        load_kv_stage(0);
        cp_commit();
    }

    float m0 = -1e30f, m1 = -1e30f, l0 = 0.f, l1 = 0.f;
    float O[8][4];
#pragma unroll
    for (int i = 0; i < 8; i++)
#pragma unroll
        for (int q = 0; q < 4; q++) O[i][q] = 0.f;
    uint32_t qfh[4][4], qfl[4][4];

    const int tr0 = t0 + wr0 + g, tr1 = tr0 + 8;
    const int tl0 = wr0 + g;                    // local row for bias smem

    for (int blk = 0; blk < NBLK; blk++) {
        // mask prefetch into registers (L2-resident; hidden under MMAs)
        float2 mk0[8], mk1[8];
        {
            const int s0g = blk * ABS;
#pragma unroll
            for (int nf = 0; nf < 8; nf++) {
                const int scol = s0g + nf * 8 + qr * 2;
                mk0[nf] = __ldg(reinterpret_cast<const float2*>(attn_mask + (size_t)tr0 * T_LEN + scol));
                mk1[nf] = __ldg(reinterpret_cast<const float2*>(attn_mask + (size_t)tr1 * T_LEN + scol));
            }
        }
        // prefetch next stage
        if (blk + 1 < NBLK) {
            load_kv_stage(blk + 1);
            cp_commit();
            cp_wait<1>();
        } else {
            cp_wait<0>();
        }
        __syncthreads();

        if (blk == 0) {
#pragma unroll
            for (int ks = 0; ks < 4; ks++) {
                uint32_t aoff = sw128((uint32_t)(wr0 + (lane & 15)) * 128 +
                                      (uint32_t)(ks * 16 + (lane >> 4) * 8) * 2);
                ldm_x4(qfh[ks], sb + AQ_H + aoff);
                ldm_x4(qfl[ks], sb + AQ_L + aoff);
            }
        }

        const uint32_t B = sb + AST0 + (uint32_t)(blk & 1) * AST_STRIDE;

        // ---- S = Q K^T (3-product split) ----
        float S[8][4];
#pragma unroll
        for (int i = 0; i < 8; i++)
#pragma unroll
            for (int q = 0; q < 4; q++) S[i][q] = 0.f;
#pragma unroll
        for (int ks = 0; ks < 4; ks++) {
#pragma unroll
            for (int nf = 0; nf < 8; nf++) {
                uint32_t boff = sw128((uint32_t)(nf * 8 + (lane & 7)) * 128 +
                                      (uint32_t)(ks * 16 + ((lane >> 3) & 1) * 8) * 2);
                uint32_t bh[2], bl[2];
                ldm_x2(bh, B + S_KH + boff);
                ldm_x2(bl, B + S_KL + boff);
                mma16816(S[nf], qfh[ks], bh);
                mma16816(S[nf], qfh[ks], bl);
                mma16816(S[nf], qfl[ks], bh);
            }
        }

        // ---- mask(reg) + bias(smem) + kpm(smem), row max ----
        const int*   kpms   = (const int*)(smc + (B - sb) + S_KPM);
        const float* bias_s = (const float*)(smc + (B - sb) + S_BIAS);
        float rmax0 = -1e30f, rmax1 = -1e30f;
#pragma unroll
        for (int nf = 0; nf < 8; nf++) {
            const int sloc = nf * 8 + qr * 2;
            const int k0 = kpms[sloc], k1 = kpms[sloc + 1];
            float2 ba = *reinterpret_cast<const float2*>(bias_s + (size_t)tl0 * BIAS_ST + sloc);
            float2 bb = *reinterpret_cast<const float2*>(bias_s + (size_t)(tl0 + 8) * BIAS_ST + sloc);
            S[nf][0] = k0 ? -1e30f : S[nf][0] + mk0[nf].x + ba.x;
            S[nf][1] = k1 ? -1e30f : S[nf][1] + mk0[nf].y + ba.y;
            S[nf][2] = k0 ? -1e30f : S[nf][2] + mk1[nf].x + bb.x;
            S[nf][3] = k1 ? -1e30f : S[nf][3] + mk1[nf].y + bb.y;
            rmax0 = fmaxf(rmax0, fmaxf(S[nf][0], S[nf][1]));
            rmax1 = fmaxf(rmax1, fmaxf(S[nf][2], S[nf][3]));
        }
        rmax0 = fmaxf(rmax0, __shfl_xor_sync(0xffffffffu, rmax0, 1));
        rmax0 = fmaxf(rmax0, __shfl_xor_sync(0xffffffffu, rmax0, 2));
        rmax1 = fmaxf(rmax1, __shfl_xor_sync(0xffffffffu, rmax1, 1));
        rmax1 = fmaxf(rmax1, __shfl_xor_sync(0xffffffffu, rmax1, 2));

        const float mn0 = fmaxf(m0, rmax0), mn1 = fmaxf(m1, rmax1);
        const float es0 = __expf(m0 - mn0), es1 = __expf(m1 - mn1);
        m0 = mn0; m1 = mn1;

        float rs0 = 0.f, rs1 = 0.f;
#pragma unroll
        for (int nf = 0; nf < 8; nf++) {
            S[nf][0] = __expf(S[nf][0] - mn0);
            S[nf][1] = __expf(S[nf][1] - mn0);
            S[nf][2] = __expf(S[nf][2] - mn1);
            S[nf][3] = __expf(S[nf][3] - mn1);
            rs0 += S[nf][0] + S[nf][1];
            rs1 += S[nf][2] + S[nf][3];
        }
        rs0 += __shfl_xor_sync(0xffffffffu, rs0, 1);
        rs0 += __shfl_xor_sync(0xffffffffu, rs0, 2);
        rs1 += __shfl_xor_sync(0xffffffffu, rs1, 1);
        rs1 += __shfl_xor_sync(0xffffffffu, rs1, 2);
        l0 = l0 * es0 + rs0;
        l1 = l1 * es1 + rs1;

#pragma unroll
        for (int i = 0; i < 8; i++) {
            O[i][0] *= es0; O[i][1] *= es0;
            O[i][2] *= es1; O[i][3] *= es1;
        }

        // ---- O += P V (3-product split) ----
#pragma unroll
        for (int kp = 0; kp < 4; kp++) {
            uint32_t ah[4], al[4];
            ah[0] = pack_hi2(S[2*kp][0],   S[2*kp][1]);
            ah[1] = pack_hi2(S[2*kp][2],   S[2*kp][3]);
            ah[2] = pack_hi2(S[2*kp+1][0], S[2*kp+1][1]);
            ah[3] = pack_hi2(S[2*kp+1][2], S[2*kp+1][3]);
            al[0] = pack_lo2(S[2*kp][0],   S[2*kp][1]);
            al[1] = pack_lo2(S[2*kp][2],   S[2*kp][3]);
            al[2] = pack_lo2(S[2*kp+1][0], S[2*kp+1][1]);
            al[3] = pack_lo2(S[2*kp+1][2], S[2*kp+1][3]);
#pragma unroll
            for (int nf2 = 0; nf2 < 8; nf2++) {
                uint32_t voff = sw128((uint32_t)(kp * 16 + (lane & 15)) * 128 +
                                      (uint32_t)nf2 * 16);
                uint32_t vh[2], vl[2];
                ldm_x2_trans(vh, B + S_VH + voff);
                ldm_x2_trans(vl, B + S_VL + voff);
                mma16816(O[nf2], ah, vh);
                mma16816(O[nf2], ah, vl);
                mma16816(O[nf2], al, vh);
            }
        }
        __syncthreads();
    }

    // ---- normalize + write bf16 hi/lo ----
    const float inv0 = 1.f / l0, inv1 = 1.f / l1;
    const size_t base0 = ((size_t)tr0 * BSZ + b) * EMBED + h * 64;
    const size_t base1 = ((size_t)tr1 * BSZ + b) * EMBED + h * 64;
#pragma unroll
    for (int nf2 = 0; nf2 < 8; nf2++) {
        const int d0 = nf2 * 8 + qr * 2;
        float v0 = O[nf2][0] * inv0, v1 = O[nf2][1] * inv0;
        float w0 = O[nf2][2] * inv1, w1 = O[nf2][3] * inv1;
        *reinterpret_cast<uint32_t*>(g_attnh + base0 + d0) = pack_hi2(v0, v1);
        *reinterpret_cast<uint32_t*>(g_attnl + base0 + d0) = pack_lo2(v0, v1);
        *reinterpret_cast<uint32_t*>(g_attnh + base1 + d0) = pack_hi2(w0, w1);
        *reinterpret_cast<uint32_t*>(g_attnl + base1 + d0) = pack_lo2(w0, w1);
    }
}

// ---------------------------------------------------------------------------
extern "C" void kernel_launch(void* const* d_in, const int* in_sizes, int n_in,
                              void* d_out, int out_size)
{
    const float* query     = (const float*)d_in[0];
    const int*   kpm       = (const int*)  d_in[1];
    const float* attn_mask = (const float*)d_in[2];
    const float* attn_bias = (const float*)d_in[3];
    const float* W_in      = (const float*)d_in[4];
    const float* b_in      = (const float*)d_in[5];
    const float* W_out     = (const float*)d_in[6];
    const float* b_out     = (const float*)d_in[7];
    float*       out       = (float*)d_out;

    static bool attr_set = false;
    if (!attr_set) {
        cudaFuncSetAttribute(gemm_mma, cudaFuncAttributeMaxDynamicSharedMemorySize, GEMM_SMEM);
        cudaFuncSetAttribute(attn_mma_kernel, cudaFuncAttributeMaxDynamicSharedMemorySize, ATTN_SMEM);
        attr_set = true;
    }

    __nv_bfloat16 *Ah, *Al, *Bh, *Bl, *ATh, *ATl;
    cudaGetSymbolAddress((void**)&Ah, g_Ah);
    cudaGetSymbolAddress((void**)&Al, g_Al);
    cudaGetSymbolAddress((void**)&Bh, g_Bh);
    cudaGetSymbolAddress((void**)&Bl, g_Bl);
    cudaGetSymbolAddress((void**)&ATh, g_attnh);
    cudaGetSymbolAddress((void**)&ATl, g_attnl);

    // 1) split query and W_in to bf16 pairs
    split_kernel<<<MROWS * EMBED / 4 / 256, 256>>>(query, Ah, Al, MROWS * EMBED / 4);
    split_kernel<<<3 * EMBED * EMBED / 4 / 256, 256>>>(W_in, Bh, Bl, 3 * EMBED * EMBED / 4);

    // 2) QKV projection -> bf16 hi/lo q,k,v
    {
        dim3 grid(3 * EMBED / TN, MROWS / TM);
        gemm_mma<<<grid, 256, GEMM_SMEM>>>(Ah, Al, Bh, Bl, b_in, 0, nullptr);
    }

    // 3) Flash attention on tensor cores -> bf16 hi/lo attn
    {
        dim3 grid(T_LEN / ABT, NBH);   // (8, 64)
        attn_mma_kernel<<<grid, 256, ATTN_SMEM>>>(kpm, attn_mask, attn_bias);
    }

    // 4) split W_out; output projection (A = attn bf16 pairs)
    split_kernel<<<EMBED * EMBED / 4 / 256, 256>>>(W_out, Bh, Bl, EMBED * EMBED / 4);
    {
        dim3 grid(EMBED / TN, MROWS / TM);
        gemm_mma<<<grid, 256, GEMM_SMEM>>>(ATh, ATl, Bh, Bl, b_out, 1, out);
    }
}